// round 3
// baseline (speedup 1.0000x reference)
#include <cuda_runtime.h>
#include <math.h>

// ---------------------------------------------------------------------------
// PCGNN R3: register-resident weights + software-pipelined gather/GEMM
// 256-thread CTAs, 2 CTAs/SM, NB=8 nodes/iter, double-buffered staging
// Shapes: N_SRC=60000, N_DST=30000, DEG=32, F=128, E=64, C=2, K=16
// ---------------------------------------------------------------------------

#define F_DIM   128
#define E_DIM   64
#define DEG     32
#define KSEL    16
#define NB      8          // nodes per block-iteration
#define ST      12         // staging stride (floats), 16B-aligned for float4
#define THREADS 256

#define N_SRC_MAX 60000
__device__ float g_sig[N_SRC_MAX];   // sigmoid(x[v]·Wd0 + b0) for every source row

// ---- score precompute: one warp per source row --------------------------------
__global__ void score_kernel(const float* __restrict__ x,
                             const float* __restrict__ Wd,   // [128,2] row-major
                             const float* __restrict__ bd,   // [2]
                             float* __restrict__ score_out,  // [n_dst,2]
                             int n_src, int n_dst) {
    int w    = (blockIdx.x * blockDim.x + threadIdx.x) >> 5;
    int lane = threadIdx.x & 31;
    if (w >= n_src) return;
    int f0 = lane * 4;
    float4 xv = *(const float4*)(x + (size_t)w * F_DIM + f0);
    float4 wA = *(const float4*)(Wd + f0 * 2);
    float4 wB = *(const float4*)(Wd + f0 * 2 + 4);
    float d0 = xv.x*wA.x + xv.y*wA.z + xv.z*wB.x + xv.w*wB.z;
    float d1 = xv.x*wA.y + xv.y*wA.w + xv.z*wB.y + xv.w*wB.w;
    #pragma unroll
    for (int o = 16; o; o >>= 1) {
        d0 += __shfl_xor_sync(0xffffffffu, d0, o);
        d1 += __shfl_xor_sync(0xffffffffu, d1, o);
    }
    if (lane == 0) {
        float s0 = d0 + bd[0];
        g_sig[w] = 1.0f / (1.0f + expf(-s0));
        if (w < n_dst) {
            score_out[(size_t)w * 2]     = s0;
            score_out[(size_t)w * 2 + 1] = d1 + bd[1];
        }
    }
}

// ---- dynamic SMEM layout (bytes), all 16B-aligned -----------------------------
#define SM_WO    0          // float2[64]   W_out rows                     512
#define SM_BS    512        // float [64]   b_sage                         256
#define SM_XD0   768        // float [128*ST]  x_dst  buf0                6144
#define SM_XD1   6912       // float [128*ST]  x_dst  buf1                6144
#define SM_HN0   13056      // float [128*ST]  h_neigh buf0               6144
#define SM_HN1   19200      // float [128*ST]  h_neigh buf1               6144
#define SM_PART  25344      // float [4*8*64]  partial sums [q][n][e]     8192
#define SM_H     33536      // float [8*64]    relu(h) [n][e]             2048
#define SM_DIFF  35584      // float [8*32]                               1024
#define SM_SEL0  36608      // int   [8*16]    selected ids buf0           512
#define SM_SEL1  37120      // int   [8*16]    selected ids buf1           512
#define SM_TOTAL 37632

__global__ __launch_bounds__(THREADS, 2)
void pcgnn_main_kernel(const float* __restrict__ x,
                       const int*   __restrict__ neighbors,
                       const float* __restrict__ W_self,   // [128,64]
                       const float* __restrict__ W_neigh,  // [128,64]
                       const float* __restrict__ b_sage,   // [64]
                       const float* __restrict__ W_out,    // [64,2]
                       const float* __restrict__ b_out,    // [2]
                       float* __restrict__ out_logits,     // [n_dst,2]
                       int n_dst) {
    extern __shared__ char sm[];
    float2* sWo   = (float2*)(sm + SM_WO);
    float*  sbs   = (float*) (sm + SM_BS);
    float*  sxd[2]; sxd[0] = (float*)(sm + SM_XD0); sxd[1] = (float*)(sm + SM_XD1);
    float*  shn[2]; shn[0] = (float*)(sm + SM_HN0); shn[1] = (float*)(sm + SM_HN1);
    float*  spart = (float*) (sm + SM_PART);
    float*  sh    = (float*) (sm + SM_H);
    float*  sdiff = (float*) (sm + SM_DIFF);
    int*    ssel[2]; ssel[0] = (int*)(sm + SM_SEL0); ssel[1] = (int*)(sm + SM_SEL1);

    const int tid  = threadIdx.x;
    const int g    = tid >> 5;        // warp 0..7
    const int lane = tid & 31;
    const int e    = tid & 63;        // output column (Phase D)
    const int q    = tid >> 6;        // f-quarter 0..3 (Phase D)
    const int f    = tid & 127;       // feature (gather)
    const int slot = tid >> 7;        // 0..1 (gather)

    // ---- loop-invariant weights into registers (once) ----
    float2 wreg[32];
    #pragma unroll
    for (int ff = 0; ff < 32; ff++) {
        const int fr = q * 32 + ff;
        wreg[ff] = make_float2(W_self[fr * E_DIM + e], W_neigh[fr * E_DIM + e]);
    }
    if (tid < E_DIM) {
        sWo[tid] = make_float2(W_out[tid * 2], W_out[tid * 2 + 1]);
        sbs[tid] = b_sage[tid];
    }
    const float bo0 = b_out[0], bo1 = b_out[1];

    const int stride = gridDim.x * NB;
    const int base0  = blockIdx.x * NB;

    // ===== select: warp g picks top-16 for node (sbase+g) into ssel[buf] =====
    auto do_select = [&](int sbase, int buf) {
        const int node = sbase + g;
        if (node < n_dst) {
            int nb = neighbors[(size_t)node * DEG + lane];
            float t = g_sig[node];
            float d = fabsf(t - g_sig[nb]);
            sdiff[g * 32 + lane] = d;
            __syncwarp();
            int rank = 0;
            #pragma unroll
            for (int j = 0; j < 32; j++) {
                float dj = sdiff[g * 32 + j];
                rank += (dj < d) || (dj == d && j < lane);
            }
            if (rank < KSEL) ssel[buf][g * KSEL + rank] = nb;
        } else if (lane < KSEL) {
            ssel[buf][g * KSEL + lane] = 0;   // safe dummy
        }
    };

    // ===== gather: mean of selected rows + x_dst into staging buf =====
    auto do_gather = [&](int gbase, int buf) {
        float* xd = sxd[buf];
        float* hn = shn[buf];
        const int* sel = ssel[buf];
        #pragma unroll
        for (int np = 0; np < 4; np++) {
            const int gg = np * 2 + slot;
            int nd = gbase + gg;
            if (nd >= n_dst) nd = n_dst - 1;
            float s0 = 0.f, s1 = 0.f, s2 = 0.f, s3 = 0.f;
            int idx[KSEL];
            #pragma unroll
            for (int k = 0; k < KSEL; k++) idx[k] = sel[gg * KSEL + k];
            #pragma unroll
            for (int k = 0; k < KSEL; k += 4) {
                s0 += x[(size_t)idx[k]     * F_DIM + f];
                s1 += x[(size_t)idx[k + 1] * F_DIM + f];
                s2 += x[(size_t)idx[k + 2] * F_DIM + f];
                s3 += x[(size_t)idx[k + 3] * F_DIM + f];
            }
            hn[f * ST + gg] = ((s0 + s1) + (s2 + s3)) * 0.0625f;
            xd[f * ST + gg] = x[(size_t)nd * F_DIM + f];
        }
    };

    // ---- prologue ----
    do_select(base0, 0);
    __syncthreads();
    do_gather(base0, 0);
    int cur = 0;

    for (int base = base0; base < n_dst; base += stride) {
        const int nxt = base + stride;
        do_select(nxt, cur ^ 1);
        __syncthreads();            // ssel[cur^1] ready; gather(cur) stores visible

        // --- gather(next) LDGs overlap with GEMM(cur) FFMAs below ---
        do_gather(nxt, cur ^ 1);

        // ---- Phase D: SAGE dual-GEMM from buf cur, weights in registers ----
        {
            const float* xd = sxd[cur];
            const float* hn = shn[cur];
            float acc[NB];
            #pragma unroll
            for (int n = 0; n < NB; n++) acc[n] = 0.f;
            #pragma unroll
            for (int ff = 0; ff < 32; ff++) {
                const int fr = q * 32 + ff;
                float2 w = wreg[ff];
                float4 xa0 = *(const float4*)(xd + fr * ST);
                float4 xa1 = *(const float4*)(xd + fr * ST + 4);
                float4 hb0 = *(const float4*)(hn + fr * ST);
                float4 hb1 = *(const float4*)(hn + fr * ST + 4);
                acc[0] = fmaf(xa0.x, w.x, fmaf(hb0.x, w.y, acc[0]));
                acc[1] = fmaf(xa0.y, w.x, fmaf(hb0.y, w.y, acc[1]));
                acc[2] = fmaf(xa0.z, w.x, fmaf(hb0.z, w.y, acc[2]));
                acc[3] = fmaf(xa0.w, w.x, fmaf(hb0.w, w.y, acc[3]));
                acc[4] = fmaf(xa1.x, w.x, fmaf(hb1.x, w.y, acc[4]));
                acc[5] = fmaf(xa1.y, w.x, fmaf(hb1.y, w.y, acc[5]));
                acc[6] = fmaf(xa1.z, w.x, fmaf(hb1.z, w.y, acc[6]));
                acc[7] = fmaf(xa1.w, w.x, fmaf(hb1.w, w.y, acc[7]));
            }
            #pragma unroll
            for (int n = 0; n < NB; n++)
                spart[(q * NB + n) * E_DIM + e] = acc[n];
        }
        __syncthreads();

        // ---- reduce quarters + bias + relu (512 elems, 2 per thread) ----
        #pragma unroll
        for (int r = 0; r < 2; r++) {
            const int p = tid + r * THREADS;
            const int n = p >> 6, ee = p & 63;
            float s = spart[(0 * NB + n) * E_DIM + ee]
                    + spart[(1 * NB + n) * E_DIM + ee]
                    + spart[(2 * NB + n) * E_DIM + ee]
                    + spart[(3 * NB + n) * E_DIM + ee]
                    + sbs[ee];
            sh[n * E_DIM + ee] = fmaxf(s, 0.f);
        }
        __syncthreads();

        // ---- Phase E: output projection, warp g -> node base+g ----
        {
            const int node = base + g;
            float h0 = sh[g * E_DIM + lane];
            float h1 = sh[g * E_DIM + 32 + lane];
            float2 w0 = sWo[lane];
            float2 w1 = sWo[lane + 32];
            float c0 = h0 * w0.x + h1 * w1.x;
            float c1 = h0 * w0.y + h1 * w1.y;
            #pragma unroll
            for (int o = 16; o; o >>= 1) {
                c0 += __shfl_xor_sync(0xffffffffu, c0, o);
                c1 += __shfl_xor_sync(0xffffffffu, c1, o);
            }
            if (lane == 0 && node < n_dst) {
                out_logits[(size_t)node * 2]     = c0 + bo0;
                out_logits[(size_t)node * 2 + 1] = c1 + bo1;
            }
        }
        cur ^= 1;
        // no barrier needed here: next select writes ssel[cur^1] (last read
        // one full iteration ago) and sdiff (per-warp, syncwarp-protected);
        // sh readers (E) vs next writers (reduce) are separated by 2 barriers.
    }
}

extern "C" void kernel_launch(void* const* d_in, const int* in_sizes, int n_in,
                              void* d_out, int out_size) {
    const float* x        = (const float*)d_in[0];
    const int*   neighbors= (const int*)  d_in[1];
    const float* W_dist   = (const float*)d_in[2];
    const float* b_dist   = (const float*)d_in[3];
    const float* W_self   = (const float*)d_in[4];
    const float* W_neigh  = (const float*)d_in[5];
    const float* b_sage   = (const float*)d_in[6];
    const float* W_out    = (const float*)d_in[7];
    const float* b_out    = (const float*)d_in[8];

    const int n_src = in_sizes[0] / F_DIM;
    const int n_dst = in_sizes[1] / DEG;

    float* out    = (float*)d_out;
    float* logits = out;                     // [n_dst, 2]
    float* score  = out + (size_t)n_dst * 2; // [n_dst, 2]

    int blocks1 = (n_src + 7) / 8;
    score_kernel<<<blocks1, 256>>>(x, W_dist, b_dist, score, n_src, n_dst);

    cudaFuncSetAttribute(pcgnn_main_kernel,
                         cudaFuncAttributeMaxDynamicSharedMemorySize, SM_TOTAL);
    pcgnn_main_kernel<<<296, THREADS, SM_TOTAL>>>(
        x, neighbors, W_self, W_neigh, b_sage, W_out, b_out, logits, n_dst);
}

// round 5
// speedup vs baseline: 1.5293x; 1.5293x over previous
#include <cuda_runtime.h>
#include <math.h>

// ---------------------------------------------------------------------------
// PCGNN R5 (= R4 re-bench after infra failure, + micro-hoist in Phase C):
// 512 thr, NB=16, 2 CTAs/SM, register-resident weights, int4 index loads.
// Shapes: N_SRC=60000, N_DST=30000, DEG=32, F=128, E=64, C=2, K=16
// ---------------------------------------------------------------------------

#define F_DIM   128
#define E_DIM   64
#define DEG     32
#define KSEL    16
#define NB      16         // nodes per block-iteration
#define ST      20         // staging stride (floats): 16B-aligned, 4-way conflicts
#define THREADS 512

#define N_SRC_MAX 60000
__device__ float g_sig[N_SRC_MAX];   // sigmoid(x[v]·Wd0 + b0) for every source row

// ---- score precompute: one warp per source row --------------------------------
__global__ void score_kernel(const float* __restrict__ x,
                             const float* __restrict__ Wd,   // [128,2] row-major
                             const float* __restrict__ bd,   // [2]
                             float* __restrict__ score_out,  // [n_dst,2]
                             int n_src, int n_dst) {
    int w    = (blockIdx.x * blockDim.x + threadIdx.x) >> 5;
    int lane = threadIdx.x & 31;
    if (w >= n_src) return;
    int f0 = lane * 4;
    float4 xv = *(const float4*)(x + (size_t)w * F_DIM + f0);
    float4 wA = *(const float4*)(Wd + f0 * 2);
    float4 wB = *(const float4*)(Wd + f0 * 2 + 4);
    float d0 = xv.x*wA.x + xv.y*wA.z + xv.z*wB.x + xv.w*wB.z;
    float d1 = xv.x*wA.y + xv.y*wA.w + xv.z*wB.y + xv.w*wB.w;
    #pragma unroll
    for (int o = 16; o; o >>= 1) {
        d0 += __shfl_xor_sync(0xffffffffu, d0, o);
        d1 += __shfl_xor_sync(0xffffffffu, d1, o);
    }
    if (lane == 0) {
        float s0 = d0 + bd[0];
        g_sig[w] = 1.0f / (1.0f + expf(-s0));
        if (w < n_dst) {
            score_out[(size_t)w * 2]     = s0;
            score_out[(size_t)w * 2 + 1] = d1 + bd[1];
        }
    }
}

// ---- dynamic SMEM layout (bytes), all 16B-aligned -----------------------------
#define SM_WO    0          // float2[64]   W_out rows                      512
#define SM_BS    512        // float [64]   b_sage                          256
#define SM_XD    768        // float [128*ST]  x_dst  [f][node]           10240
#define SM_HN    11008      // float [128*ST]  h_neigh [f][node]          10240
#define SM_PART  21248      // float [8*16*64] partials [oct][n][e]       32768
#define SM_H     54016      // float [16*64]   relu(h) [n][e]              4096
#define SM_DIFF  58112      // float [16*32]                               2048
#define SM_SEL   60160      // int   [16*16]   selected neighbor ids       1024
#define SM_TOTAL 61184

__global__ __launch_bounds__(THREADS, 2)
void pcgnn_main_kernel(const float* __restrict__ x,
                       const int*   __restrict__ neighbors,
                       const float* __restrict__ W_self,   // [128,64]
                       const float* __restrict__ W_neigh,  // [128,64]
                       const float* __restrict__ b_sage,   // [64]
                       const float* __restrict__ W_out,    // [64,2]
                       const float* __restrict__ b_out,    // [2]
                       float* __restrict__ out_logits,     // [n_dst,2]
                       int n_dst) {
    extern __shared__ char sm[];
    float2* sWo   = (float2*)(sm + SM_WO);
    float*  sbs   = (float*) (sm + SM_BS);
    float*  sxd   = (float*) (sm + SM_XD);
    float*  shn   = (float*) (sm + SM_HN);
    float*  spart = (float*) (sm + SM_PART);
    float*  sh    = (float*) (sm + SM_H);
    float*  sdiff = (float*) (sm + SM_DIFF);
    int*    ssel  = (int*)   (sm + SM_SEL);

    const int tid  = threadIdx.x;
    const int g    = tid >> 5;        // warp 0..15
    const int lane = tid & 31;
    const int e    = tid & 63;        // output column (Phase D / wreg)
    const int oct  = tid >> 6;        // f-sixteenth 0..7 (Phase D)
    const int f    = tid & 127;       // feature (gather)
    const int slot = tid >> 7;        // 0..3 (gather)

    // ---- loop-invariant weights into registers: 16 f x (Ws,Wn) for column e ----
    float2 wreg[16];
    #pragma unroll
    for (int ff = 0; ff < 16; ff++) {
        const int fr = oct * 16 + ff;
        wreg[ff] = make_float2(W_self[fr * E_DIM + e], W_neigh[fr * E_DIM + e]);
    }
    if (tid < E_DIM) {
        sWo[tid] = make_float2(W_out[tid * 2], W_out[tid * 2 + 1]);
        sbs[tid] = b_sage[tid];
    }
    const float bo0 = b_out[0], bo1 = b_out[1];

    for (int base = blockIdx.x * NB; base < n_dst; base += gridDim.x * NB) {
        // ---- Phase A: select — warp g picks top-16 for node base+g ----
        {
            const int node = base + g;
            if (node < n_dst) {
                int nb = neighbors[(size_t)node * DEG + lane];
                float t = g_sig[node];
                float d = fabsf(t - g_sig[nb]);
                sdiff[g * 32 + lane] = d;
                __syncwarp();
                int rank = 0;
                #pragma unroll
                for (int j = 0; j < 32; j++) {
                    float dj = sdiff[g * 32 + j];
                    rank += (dj < d) || (dj == d && j < lane);
                }
                if (rank < KSEL) ssel[g * KSEL + rank] = nb;
            } else if (lane < KSEL) {
                ssel[g * KSEL + lane] = 0;   // safe dummy
            }
        }
        __syncthreads();

        // ---- Phase C: gather means + x_dst, thread = (f, slot of 4 nodes) ----
        {
            #pragma unroll
            for (int np = 0; np < 4; np++) {
                const int gg = np * 4 + slot;
                int nd = base + gg;
                if (nd >= n_dst) nd = n_dst - 1;
                // hoist x_dst load so its scoreboard overlaps the 16 gathers
                float xdv = x[(size_t)nd * F_DIM + f];
                const int4* sp = (const int4*)(ssel + gg * KSEL);
                int4 iA = sp[0], iB = sp[1], iC = sp[2], iD = sp[3];
                float s0, s1, s2, s3;
                s0  = x[(size_t)iA.x * F_DIM + f];
                s1  = x[(size_t)iA.y * F_DIM + f];
                s2  = x[(size_t)iA.z * F_DIM + f];
                s3  = x[(size_t)iA.w * F_DIM + f];
                s0 += x[(size_t)iB.x * F_DIM + f];
                s1 += x[(size_t)iB.y * F_DIM + f];
                s2 += x[(size_t)iB.z * F_DIM + f];
                s3 += x[(size_t)iB.w * F_DIM + f];
                s0 += x[(size_t)iC.x * F_DIM + f];
                s1 += x[(size_t)iC.y * F_DIM + f];
                s2 += x[(size_t)iC.z * F_DIM + f];
                s3 += x[(size_t)iC.w * F_DIM + f];
                s0 += x[(size_t)iD.x * F_DIM + f];
                s1 += x[(size_t)iD.y * F_DIM + f];
                s2 += x[(size_t)iD.z * F_DIM + f];
                s3 += x[(size_t)iD.w * F_DIM + f];
                shn[f * ST + gg] = ((s0 + s1) + (s2 + s3)) * 0.0625f;
                sxd[f * ST + gg] = xdv;
            }
        }
        __syncthreads();

        // ---- Phase D: SAGE dual-GEMM, weights in regs, 2 passes of 8 nodes ----
        #pragma unroll
        for (int h = 0; h < 2; h++) {
            const int n0 = h * 8;
            float acc[8];
            #pragma unroll
            for (int n = 0; n < 8; n++) acc[n] = 0.f;
            #pragma unroll
            for (int ff = 0; ff < 16; ff++) {
                const int fr = oct * 16 + ff;
                float2 w = wreg[ff];
                float4 xa0 = *(const float4*)(sxd + fr * ST + n0);
                float4 xa1 = *(const float4*)(sxd + fr * ST + n0 + 4);
                float4 hb0 = *(const float4*)(shn + fr * ST + n0);
                float4 hb1 = *(const float4*)(shn + fr * ST + n0 + 4);
                acc[0] = fmaf(xa0.x, w.x, fmaf(hb0.x, w.y, acc[0]));
                acc[1] = fmaf(xa0.y, w.x, fmaf(hb0.y, w.y, acc[1]));
                acc[2] = fmaf(xa0.z, w.x, fmaf(hb0.z, w.y, acc[2]));
                acc[3] = fmaf(xa0.w, w.x, fmaf(hb0.w, w.y, acc[3]));
                acc[4] = fmaf(xa1.x, w.x, fmaf(hb1.x, w.y, acc[4]));
                acc[5] = fmaf(xa1.y, w.x, fmaf(hb1.y, w.y, acc[5]));
                acc[6] = fmaf(xa1.z, w.x, fmaf(hb1.z, w.y, acc[6]));
                acc[7] = fmaf(xa1.w, w.x, fmaf(hb1.w, w.y, acc[7]));
            }
            #pragma unroll
            for (int n = 0; n < 8; n++)
                spart[(oct * NB + n0 + n) * E_DIM + e] = acc[n];
        }
        __syncthreads();

        // ---- reduce octs + bias + relu (1024 outputs, 2 per thread) ----
        #pragma unroll
        for (int r = 0; r < 2; r++) {
            const int p  = tid + r * THREADS;
            const int n  = p >> 6, ee = p & 63;
            float a0 = spart[(0 * NB + n) * E_DIM + ee]
                     + spart[(1 * NB + n) * E_DIM + ee];
            float a1 = spart[(2 * NB + n) * E_DIM + ee]
                     + spart[(3 * NB + n) * E_DIM + ee];
            float a2 = spart[(4 * NB + n) * E_DIM + ee]
                     + spart[(5 * NB + n) * E_DIM + ee];
            float a3 = spart[(6 * NB + n) * E_DIM + ee]
                     + spart[(7 * NB + n) * E_DIM + ee];
            float s = (a0 + a1) + (a2 + a3) + sbs[ee];
            sh[n * E_DIM + ee] = fmaxf(s, 0.f);
        }
        __syncthreads();

        // ---- Phase E: output projection, warp g -> node base+g ----
        {
            const int node = base + g;
            float h0 = sh[g * E_DIM + lane];
            float h1 = sh[g * E_DIM + 32 + lane];
            float2 w0 = sWo[lane];
            float2 w1 = sWo[lane + 32];
            float c0 = h0 * w0.x + h1 * w1.x;
            float c1 = h0 * w0.y + h1 * w1.y;
            #pragma unroll
            for (int o = 16; o; o >>= 1) {
                c0 += __shfl_xor_sync(0xffffffffu, c0, o);
                c1 += __shfl_xor_sync(0xffffffffu, c1, o);
            }
            if (lane == 0 && node < n_dst) {
                out_logits[(size_t)node * 2]     = c0 + bo0;
                out_logits[(size_t)node * 2 + 1] = c1 + bo1;
            }
        }
        // no barrier: next select writes ssel/sdiff — ssel last read before
        // Phase-C barrier (3 barriers ago); sh readers (E) vs writers (reduce)
        // are 2 barriers apart.
    }
}

extern "C" void kernel_launch(void* const* d_in, const int* in_sizes, int n_in,
                              void* d_out, int out_size) {
    const float* x        = (const float*)d_in[0];
    const int*   neighbors= (const int*)  d_in[1];
    const float* W_dist   = (const float*)d_in[2];
    const float* b_dist   = (const float*)d_in[3];
    const float* W_self   = (const float*)d_in[4];
    const float* W_neigh  = (const float*)d_in[5];
    const float* b_sage   = (const float*)d_in[6];
    const float* W_out    = (const float*)d_in[7];
    const float* b_out    = (const float*)d_in[8];

    const int n_src = in_sizes[0] / F_DIM;
    const int n_dst = in_sizes[1] / DEG;

    float* out    = (float*)d_out;
    float* logits = out;                     // [n_dst, 2]
    float* score  = out + (size_t)n_dst * 2; // [n_dst, 2]

    int blocks1 = (n_src + 7) / 8;
    score_kernel<<<blocks1, 256>>>(x, W_dist, b_dist, score, n_src, n_dst);

    cudaFuncSetAttribute(pcgnn_main_kernel,
                         cudaFuncAttributeMaxDynamicSharedMemorySize, SM_TOTAL);
    pcgnn_main_kernel<<<296, THREADS, SM_TOTAL>>>(
        x, neighbors, W_self, W_neigh, b_sage, W_out, b_out, logits, n_dst);
}